// round 2
// baseline (speedup 1.0000x reference)
#include <cuda_runtime.h>

#define N_USERS 40000
#define N_ITEMS 60000
#define N_NODES 100000
#define N_EDGES 1280000
#define EMB 64
#define NEG_SLOPE 0.2f

// ---------------- scratch (static device globals; no allocs) ----------------
__device__ float g_e[N_NODES * EMB];      // current layer embeddings
__device__ float g_x[N_NODES * EMB];      // spmm result
__device__ float g_acc[N_NODES * EMB];    // running sum
__device__ int   g_rowptr[N_NODES + 1];
__device__ int   g_cursor[N_NODES];       // counts, then scatter cursors
__device__ int   g_bsum[256];             // scan block sums
__device__ int   g_cols[N_EDGES];
__device__ float g_vals[N_EDGES];

// -------- init: e = acc = concat(user, item); also zero CSR counters --------
__global__ void k_init(const float* __restrict__ user, const float* __restrict__ item) {
    int i = blockIdx.x * blockDim.x + threadIdx.x;           // float4 index
    if (i < N_NODES) g_cursor[i] = 0;                        // fused counter zero
    const int total4 = (N_NODES * EMB) / 4;
    if (i >= total4) return;
    const int u4 = (N_USERS * EMB) / 4;
    float4 v = (i < u4) ? ((const float4*)user)[i] : ((const float4*)item)[i - u4];
    ((float4*)g_e)[i]   = v;
    ((float4*)g_acc)[i] = v;
}

// ---------------- CSR build ----------------
__global__ void k_hist(const int* __restrict__ row) {
    int i = blockIdx.x * blockDim.x + threadIdx.x;
    if (i < N_EDGES) atomicAdd(&g_cursor[row[i]], 1);
}

// pass 1: per-block inclusive scan of 512-element chunk; write exclusive partials
__global__ void k_scan1() {
    __shared__ int s[512];
    int t = threadIdx.x;
    int idx = blockIdx.x * 512 + t;
    int val = (idx < N_NODES) ? g_cursor[idx] : 0;
    s[t] = val;
    __syncthreads();
    #pragma unroll
    for (int off = 1; off < 512; off <<= 1) {
        int v = (t >= off) ? s[t - off] : 0;
        __syncthreads();
        s[t] += v;
        __syncthreads();
    }
    if (idx < N_NODES) g_rowptr[idx] = s[t] - val;  // exclusive partial
    if (t == 511) g_bsum[blockIdx.x] = s[511];
}

// pass 2: serial exclusive scan of block sums (tiny: 196 values)
__global__ void k_scan2(int nblocks) {
    if (threadIdx.x == 0 && blockIdx.x == 0) {
        int run = 0;
        for (int b = 0; b < nblocks; b++) {
            int v = g_bsum[b];
            g_bsum[b] = run;
            run += v;
        }
    }
}

// pass 3: add block offsets, copy to scatter cursor, finalize rowptr[N]
__global__ void k_scan3() {
    int t = threadIdx.x;
    int idx = blockIdx.x * 512 + t;
    if (idx < N_NODES) {
        int v = g_rowptr[idx] + g_bsum[blockIdx.x];
        g_rowptr[idx] = v;
        g_cursor[idx] = v;
    }
    if (idx == 0) g_rowptr[N_NODES] = N_EDGES;
}

__global__ void k_scatter(const int* __restrict__ row, const int* __restrict__ col,
                          const float* __restrict__ val) {
    int i = blockIdx.x * blockDim.x + threadIdx.x;
    if (i >= N_EDGES) return;
    int r = row[i];
    int pos = atomicAdd(&g_cursor[r], 1);
    g_cols[pos] = col[i];
    g_vals[pos] = val[i];
}

// ---------------- SpMM: x[r] = sum_j val_j * e[col_j]  (warp per row) --------
// two independent fma chains per lane (even/odd j) for extra MLP
__global__ void k_spmm() {
    int r = blockIdx.x * 8 + (threadIdx.x >> 5);
    if (r >= N_NODES) return;
    int lane = threadIdx.x & 31;
    int s = g_rowptr[r];
    int t = g_rowptr[r + 1];
    float ax0 = 0.f, ay0 = 0.f, ax1 = 0.f, ay1 = 0.f;
    int j = s;
    for (; j + 1 < t; j += 2) {
        int   c0 = g_cols[j];
        int   c1 = g_cols[j + 1];
        float v0 = g_vals[j];
        float v1 = g_vals[j + 1];
        float2 e0 = *(const float2*)&g_e[c0 * EMB + lane * 2];
        float2 e1 = *(const float2*)&g_e[c1 * EMB + lane * 2];
        ax0 = fmaf(v0, e0.x, ax0);
        ay0 = fmaf(v0, e0.y, ay0);
        ax1 = fmaf(v1, e1.x, ax1);
        ay1 = fmaf(v1, e1.y, ay1);
    }
    if (j < t) {
        int   c = g_cols[j];
        float v = g_vals[j];
        float2 ev = *(const float2*)&g_e[c * EMB + lane * 2];
        ax0 = fmaf(v, ev.x, ax0);
        ay0 = fmaf(v, ev.y, ay0);
    }
    *(float2*)&g_x[r * EMB + lane * 2] = make_float2(ax0 + ax1, ay0 + ay1);
}

// ---------------- Dense: h = (e+x)@W1 + (x*e)@W2 + b1+b2; leaky; l2norm ------
// block: 256 threads, 128-node tile. thread tile: 4 nodes x 8 cols.
// dynamic smem: sA1[128*65] sA2[128*65] sW1[4096] sW2[4096]  = 99328 B
#define A_STRIDE 65
__global__ void __launch_bounds__(256) k_dense(const float* __restrict__ W1,
                                               const float* __restrict__ b1,
                                               const float* __restrict__ W2,
                                               const float* __restrict__ b2) {
    extern __shared__ float sm[];
    float* sA1 = sm;                       // 128*65
    float* sA2 = sm + 128 * A_STRIDE;      // 128*65
    float* sW1 = sm + 2 * 128 * A_STRIDE;  // 4096
    float* sW2 = sW1 + 4096;               // 4096

    const int node0 = blockIdx.x * 128;
    const int tid = threadIdx.x;

    // load W tiles (float4 copy, layout [d][k] contiguous)
    for (int i = tid; i < 1024; i += 256) {
        ((float4*)sW1)[i] = ((const float4*)W1)[i];
        ((float4*)sW2)[i] = ((const float4*)W2)[i];
    }
    // load A tiles: a1 = e + x, a2 = e * x (stride-65 kills bank conflicts)
    for (int i = tid; i < 2048; i += 256) {
        int r  = i >> 4;
        int c4 = (i & 15) * 4;
        int n  = node0 + r;
        float4 ev = make_float4(0.f, 0.f, 0.f, 0.f);
        float4 xv = ev;
        if (n < N_NODES) {
            ev = *(const float4*)&g_e[n * EMB + c4];
            xv = *(const float4*)&g_x[n * EMB + c4];
        }
        float* p1 = &sA1[r * A_STRIDE + c4];
        float* p2 = &sA2[r * A_STRIDE + c4];
        p1[0] = ev.x + xv.x; p1[1] = ev.y + xv.y; p1[2] = ev.z + xv.z; p1[3] = ev.w + xv.w;
        p2[0] = ev.x * xv.x; p2[1] = ev.y * xv.y; p2[2] = ev.z * xv.z; p2[3] = ev.w * xv.w;
    }
    __syncthreads();

    const int tn = (tid >> 3) * 4;   // node base in tile (0..124)
    const int tk = (tid & 7) * 8;    // col base (0..56)

    float racc[4][8];
    #pragma unroll
    for (int i = 0; i < 4; i++)
        #pragma unroll
        for (int j = 0; j < 8; j++) racc[i][j] = 0.f;

    #pragma unroll 4
    for (int d = 0; d < 64; d++) {
        float4 w1a = *(const float4*)&sW1[d * 64 + tk];
        float4 w1b = *(const float4*)&sW1[d * 64 + tk + 4];
        float4 w2a = *(const float4*)&sW2[d * 64 + tk];
        float4 w2b = *(const float4*)&sW2[d * 64 + tk + 4];
        #pragma unroll
        for (int i = 0; i < 4; i++) {
            float a1 = sA1[(tn + i) * A_STRIDE + d];
            float a2 = sA2[(tn + i) * A_STRIDE + d];
            racc[i][0] = fmaf(a1, w1a.x, fmaf(a2, w2a.x, racc[i][0]));
            racc[i][1] = fmaf(a1, w1a.y, fmaf(a2, w2a.y, racc[i][1]));
            racc[i][2] = fmaf(a1, w1a.z, fmaf(a2, w2a.z, racc[i][2]));
            racc[i][3] = fmaf(a1, w1a.w, fmaf(a2, w2a.w, racc[i][3]));
            racc[i][4] = fmaf(a1, w1b.x, fmaf(a2, w2b.x, racc[i][4]));
            racc[i][5] = fmaf(a1, w1b.y, fmaf(a2, w2b.y, racc[i][5]));
            racc[i][6] = fmaf(a1, w1b.z, fmaf(a2, w2b.z, racc[i][6]));
            racc[i][7] = fmaf(a1, w1b.w, fmaf(a2, w2b.w, racc[i][7]));
        }
    }

    // bias + leaky relu, stage h back into sA1 (reuse)
    float bs[8];
    #pragma unroll
    for (int j = 0; j < 8; j++) bs[j] = b1[tk + j] + b2[tk + j];
    __syncthreads();   // all reads of sA1/sA2 complete before overwrite
    #pragma unroll
    for (int i = 0; i < 4; i++) {
        #pragma unroll
        for (int j = 0; j < 8; j++) {
            float h = racc[i][j] + bs[j];
            h = (h >= 0.f) ? h : NEG_SLOPE * h;
            sA1[(tn + i) * A_STRIDE + tk + j] = h;
        }
    }
    __syncthreads();

    // per-row L2 normalize + update e, acc  (warp per row, 16 rows/warp)
    int w = tid >> 5, lane = tid & 31;
    for (int rr = w; rr < 128; rr += 8) {
        int n = node0 + rr;
        float h0 = sA1[rr * A_STRIDE + lane * 2];
        float h1 = sA1[rr * A_STRIDE + lane * 2 + 1];
        float ss = h0 * h0 + h1 * h1;
        #pragma unroll
        for (int off = 16; off; off >>= 1) ss += __shfl_xor_sync(0xffffffffu, ss, off);
        float norm  = sqrtf(ss);
        float scale = 1.0f / fmaxf(norm, 1e-12f);
        if (n < N_NODES) {
            float e0 = h0 * scale, e1 = h1 * scale;
            float2 a = *(const float2*)&g_acc[n * EMB + lane * 2];
            *(float2*)&g_e[n * EMB + lane * 2]   = make_float2(e0, e1);
            *(float2*)&g_acc[n * EMB + lane * 2] = make_float2(a.x + e0, a.y + e1);
        }
    }
}

// ---------------- final: out = acc / 4 ----------------
__global__ void k_final(float* __restrict__ out) {
    int i = blockIdx.x * blockDim.x + threadIdx.x;
    const int total4 = (N_NODES * EMB) / 4;
    if (i >= total4) return;
    float4 v = ((const float4*)g_acc)[i];
    v.x *= 0.25f; v.y *= 0.25f; v.z *= 0.25f; v.w *= 0.25f;
    ((float4*)out)[i] = v;
}

// ---------------- launch ----------------
extern "C" void kernel_launch(void* const* d_in, const int* in_sizes, int n_in,
                              void* d_out, int out_size) {
    const int*   edge_row = (const int*)d_in[0];
    const int*   edge_col = (const int*)d_in[1];
    const float* edge_val = (const float*)d_in[2];
    const float* user_emb = (const float*)d_in[3];
    const float* item_emb = (const float*)d_in[4];
    const float* W1 = (const float*)d_in[5];
    const float* b1 = (const float*)d_in[6];
    const float* W2 = (const float*)d_in[7];
    const float* b2 = (const float*)d_in[8];
    float* out = (float*)d_out;

    const int dense_smem = (2 * 128 * A_STRIDE + 2 * 4096) * (int)sizeof(float); // 99328 B
    cudaFuncSetAttribute(k_dense, cudaFuncAttributeMaxDynamicSharedMemorySize, dense_smem);

    const int scan_blocks = (N_NODES + 511) / 512;  // 196

    k_init<<<(N_NODES * EMB / 4 + 255) / 256, 256>>>(user_emb, item_emb);
    k_hist<<<(N_EDGES + 255) / 256, 256>>>(edge_row);
    k_scan1<<<scan_blocks, 512>>>();
    k_scan2<<<1, 32>>>(scan_blocks);
    k_scan3<<<scan_blocks, 512>>>();
    k_scatter<<<(N_EDGES + 255) / 256, 256>>>(edge_row, edge_col, edge_val);

    for (int layer = 0; layer < 3; layer++) {
        k_spmm<<<(N_NODES + 7) / 8, 256>>>();
        k_dense<<<(N_NODES + 127) / 128, 256, dense_smem>>>(
            W1 + layer * EMB * EMB, b1 + layer * EMB,
            W2 + layer * EMB * EMB, b2 + layer * EMB);
    }

    k_final<<<(N_NODES * EMB / 4 + 255) / 256, 256>>>(out);
    (void)in_sizes; (void)n_in; (void)out_size;
}